// round 7
// baseline (speedup 1.0000x reference)
#include <cuda_runtime.h>
#include <cuda_bf16.h>
#include <cstdint>

// EmbeddingBagCollection: F=8 tables [N=200000, D=64] f32, values [F, T=163840] i32,
// offsets [F, B+1=8193] i32. Output [B=8192, F*D=512] f32.
//
// R7 (= R6 retry, infra failure last round; K_MAX 8->4):
// chunked bag-per-warp to kill straggler imbalance.
//  - Work item = (chunk k, feature f, bag b), K_MAX=4 chunks of 32 indices.
//    Every active warp does at most 16 pair-loads (one chunk), all in flight.
//  - Pair loading: half-warps take even/odd rows, lane = float4 slot
//    (16 lanes x 16B = 256B row) -> 2 rows per LDG.128, predicated full unroll.
//  - k-major ordering: wave 0 (k=0) fully active + feature-contiguous for L2;
//    later waves mostly early-exit (2 cached offset loads).
//  - Bags contained in chunk 0 -> plain store; split bags -> atomicAdd (REDG)
//    over a pre-zeroed output. Last chunk loops to cover pathological bags
//    (P(len>128) ~ 1.7e-3, negligible).

static constexpr int F = 8;
static constexpr int B = 8192;
static constexpr int N = 200000;
static constexpr int D = 64;
static constexpr int T = 163840;
static constexpr int K_MAX = 4;                 // chunks per bag (covers len <= 128)
static constexpr unsigned FULL = 0xffffffffu;

__global__ __launch_bounds__(512)
void ebc_zero_kernel(float4* __restrict__ out, int n4)
{
    const int i = blockIdx.x * blockDim.x + threadIdx.x;
    if (i < n4) out[i] = make_float4(0.f, 0.f, 0.f, 0.f);
}

__global__ __launch_bounds__(256, 4)
void ebc_gather_kernel(const float* __restrict__ tables,
                       const int*   __restrict__ values,
                       const int*   __restrict__ offsets,
                       float*       __restrict__ out)
{
    const int gwarp = (blockIdx.x * blockDim.x + threadIdx.x) >> 5;
    const int lane  = threadIdx.x & 31;

    const int k  = gwarp >> 16;                 // F*B = 65536 = 2^16
    const int fb = gwarp & 0xffff;
    const int f  = fb >> 13;                    // B = 8192 = 2^13
    const int b  = fb & (B - 1);

    const int* __restrict__ offs = offsets + f * (B + 1);
    const int start = __ldg(offs + b);
    const int end   = __ldg(offs + b + 1);

    const int cbeg = start + 32 * k;
    if (cbeg >= end) return;                    // nothing for this chunk (or empty bag)

    // Normal chunks cover 32 indices; the last chunk sweeps to `end` (rare >1 iter).
    const int cend = (k == K_MAX - 1) ? end : min(end, cbeg + 32);

    const int half = lane >> 4;                 // 0: even rows, 1: odd rows
    const int hl   = lane & 15;                 // float4 slot within a row

    const int* __restrict__ vals = values + (size_t)f * T;
    const float4* __restrict__ tab4 =
        reinterpret_cast<const float4*>(tables + (size_t)f * N * D);  // 16 float4/row

    float4 acc = make_float4(0.f, 0.f, 0.f, 0.f);

    int i = cbeg;
    while (i < cend) {
        const int rem   = cend - i;
        const int chunk = rem < 32 ? rem : 32;

        const int src = lane < chunk ? lane : 0;
        const int idx = __ldg(vals + i + src);  // coalesced index prefetch

#pragma unroll
        for (int p = 0; p < 16; ++p) {
            const int rp = 2 * p + half;        // row position within chunk
            const int r  = __shfl_sync(FULL, idx, rp & 31);
            if (rp < chunk) {
                const float4 v = __ldg(tab4 + (size_t)r * 16 + hl);
                acc.x += v.x; acc.y += v.y; acc.z += v.z; acc.w += v.w;
            }
        }
        i += chunk;
    }

    // Merge even/odd-row partial sums across half-warps.
    acc.x += __shfl_xor_sync(FULL, acc.x, 16);
    acc.y += __shfl_xor_sync(FULL, acc.y, 16);
    acc.z += __shfl_xor_sync(FULL, acc.z, 16);
    acc.w += __shfl_xor_sync(FULL, acc.w, 16);

    if (lane < 16) {
        float* __restrict__ o = out + (size_t)b * (F * D) + f * D + hl * 4;
        if (k == 0 && end <= start + 32) {
            // Sole writer for this bag: plain coalesced 256B store.
            *reinterpret_cast<float4*>(o) = acc;
        } else {
            atomicAdd(o + 0, acc.x);
            atomicAdd(o + 1, acc.y);
            atomicAdd(o + 2, acc.z);
            atomicAdd(o + 3, acc.w);
        }
    }
}

extern "C" void kernel_launch(void* const* d_in, const int* in_sizes, int n_in,
                              void* d_out, int out_size)
{
    const float* tables  = (const float*)d_in[0];  // [F, N, D]
    const int*   values  = (const int*)  d_in[1];  // [F, T]
    const int*   offsets = (const int*)  d_in[2];  // [F, B+1]
    float*       out     = (float*)d_out;          // [B, F*D]

    // Zero output (poisoned to 0xAA; empty bags + atomic targets need zeros).
    const int n4 = (B * F * D) / 4;                // 1,048,576 float4
    ebc_zero_kernel<<<(n4 + 511) / 512, 512>>>((float4*)out, n4);

    // Gather: K_MAX * F * B warps = 262144, 8 warps/block -> 32768 blocks.
    const int total_warps = K_MAX * F * B;
    const int threads = 256;
    const int blocks = (total_warps * 32) / threads;
    ebc_gather_kernel<<<blocks, threads>>>(tables, values, offsets, out);
}